// round 9
// baseline (speedup 1.0000x reference)
#include <cuda_runtime.h>

#define NQ   512
#define NK   1024
#define DIMC 256
#define NH   8
#define HD   32
#define RPE  512
#define NSEG (RPE + 1)
#define KSEG 512
#define SPLIT 2
#define NB   2048

typedef unsigned long long u64;

// ---- packed f32x2 helpers (Blackwell) ----
__device__ __forceinline__ u64 pk2(float lo, float hi) {
    u64 r; asm("mov.b64 %0, {%1, %2};" : "=l"(r) : "f"(lo), "f"(hi)); return r;
}
__device__ __forceinline__ void fma2(u64& d, u64 a, u64 b) {
    asm("fma.rn.f32x2 %0, %1, %2, %0;" : "+l"(d) : "l"(a), "l"(b));
}
__device__ __forceinline__ float2 up2(u64 d) {
    float2 f; asm("mov.b64 {%0, %1}, %2;" : "=f"(f.x), "=f"(f.y) : "l"(d)); return f;
}

// ---------------- scratch ----------------
static __device__ float          g_tsort[RPE];
static __device__ unsigned short g_bstart[NB + 1];
static __device__ float          g_A[NH * NSEG];
static __device__ float          g_C[NH * NSEG];
static __device__ unsigned short g_seg[NQ * NK];
static __device__ float          g_q[NQ * DIMC];
static __device__ float          g_k[NK * DIMC];
static __device__ float          g_v[NK * DIMC];
static __device__ float          g_pO[SPLIT * NQ * DIMC];
static __device__ float          g_pm[SPLIT * NH * NQ];
static __device__ float          g_ps[SPLIT * NH * NQ];

// =============================================================================
// Kernel 1: PWL CPB bias tables (rank-sort) + bucket LUT for fast seg lookup.
// =============================================================================
__global__ void pwl_build(const float* __restrict__ W1, const float* __restrict__ b1,
                          const float* __restrict__ W2) {
    __shared__ float key[RPE];
    __shared__ float skey[RPE];
    __shared__ int   sidx[RPE];
    __shared__ float sW1[RPE], sb1[RPE];
    __shared__ float sW2[RPE * NH];

    const int tid = threadIdx.x;
    float w = W1[tid], b = b1[tid];
    float t;
    if (w != 0.0f) t = -b / w;
    else t = (b > 0.0f) ? -__int_as_float(0x7f800000) : __int_as_float(0x7f800000);
    key[tid] = t;
    sW1[tid] = w;
    sb1[tid] = b;
#pragma unroll
    for (int h = 0; h < NH; h++) sW2[tid * NH + h] = W2[tid * NH + h];
    __syncthreads();

    int rank = 0;
    float ki = t;
#pragma unroll 4
    for (int j4 = 0; j4 < RPE / 4; j4++) {
        float4 kj = *(const float4*)&key[j4 * 4];
        int j = j4 * 4;
        rank += (kj.x < ki) || (kj.x == ki && (j + 0) < tid);
        rank += (kj.y < ki) || (kj.y == ki && (j + 1) < tid);
        rank += (kj.z < ki) || (kj.z == ki && (j + 2) < tid);
        rank += (kj.w < ki) || (kj.w == ki && (j + 3) < tid);
    }
    skey[rank] = ki;
    sidx[rank] = tid;
    __syncthreads();
    g_tsort[tid] = skey[tid];

    // ---- bucket LUT: g_bstart[b] = #breakpoints < (-8 + b/128) ----
#pragma unroll
    for (int b4 = 0; b4 < 4; b4++) {
        int bb = tid * 4 + b4;
        float edge = -8.0f + (float)bb * 0.0078125f;
        int lo = 0, hi = RPE;
        while (lo < hi) {
            int mid = (lo + hi) >> 1;
            if (skey[mid] < edge) lo = mid + 1; else hi = mid;
        }
        g_bstart[bb] = (unsigned short)lo;
    }
    if (tid == 0) {
        float edge = 8.0f;
        int lo = 0, hi = RPE;
        while (lo < hi) {
            int mid = (lo + hi) >> 1;
            if (skey[mid] < edge) lo = mid + 1; else hi = mid;
        }
        g_bstart[NB] = (unsigned short)lo;
    }

    const int warp = tid >> 5, lane = tid & 31;
    if (warp < NH) {
        const int h = warp;
        float eA[16], eC[16];
        float leA = 0.f, leC = 0.f, mA = 0.f, mC = 0.f;
#pragma unroll
        for (int pp = 0; pp < 16; pp++) {
            int p = lane * 16 + pp;
            int r = sidx[p];
            float w1 = sW1[r], bb = sb1[r], w2 = sW2[r * NH + h];
            float ca, cc; bool plus;
            if (w1 > 0.f)      { plus = true;  ca = w1 * w2; cc = bb * w2; }
            else if (w1 < 0.f) { plus = false; ca = w1 * w2; cc = bb * w2; }
            else               { plus = true;  ca = 0.f;     cc = (bb > 0.f) ? bb * w2 : 0.f; }
            float ea = plus ? ca : -ca;
            float ec = plus ? cc : -cc;
            eA[pp] = ea; eC[pp] = ec;
            leA += ea; leC += ec;
            if (!plus) { mA += ca; mC += cc; }
        }
        float inA = leA, inC = leC;
#pragma unroll
        for (int o = 1; o < 32; o <<= 1) {
            float ta = __shfl_up_sync(0xffffffffu, inA, o);
            float tc = __shfl_up_sync(0xffffffffu, inC, o);
            if (lane >= o) { inA += ta; inC += tc; }
        }
        float exA = inA - leA, exC = inC - leC;
#pragma unroll
        for (int o = 16; o > 0; o >>= 1) {
            mA += __shfl_xor_sync(0xffffffffu, mA, o);
            mC += __shfl_xor_sync(0xffffffffu, mC, o);
        }
        if (lane == 0) { g_A[h * NSEG] = mA; g_C[h * NSEG] = mC; }
        float runA = exA, runC = exC;
#pragma unroll
        for (int pp = 0; pp < 16; pp++) {
            runA += eA[pp]; runC += eC[pp];
            int s = lane * 16 + pp + 1;
            g_A[h * NSEG + s] = mA + runA;
            g_C[h * NSEG + s] = mC + runC;
        }
    }
}

// =============================================================================
// Kernel 2: segment index per (q,k) — bucket LUT narrows search to ~0-1 steps.
// =============================================================================
__global__ void seg_kernel(const float* __restrict__ am) {
    __shared__ float ts[RPE];
    __shared__ unsigned short bs[NB + 4];
    int t = threadIdx.x;
    ts[t] = g_tsort[t];
    ts[t + 256] = g_tsort[t + 256];
    for (int i = t; i < NB + 1; i += 256) bs[i] = g_bstart[i];
    __syncthreads();
    int i0 = (blockIdx.x * 256 + t) * 4;
    float4 m4 = *(const float4*)&am[i0];
    float mv[4] = {m4.x, m4.y, m4.z, m4.w};
    unsigned short sg[4];
#pragma unroll
    for (int e = 0; e < 4; e++) {
        float m = mv[e];
        int lo, hi;
        if (m < -8.0f)      { lo = 0;      hi = bs[0]; }
        else if (m >= 8.0f) { lo = bs[NB]; hi = RPE; }
        else {
            int b = (int)((m + 8.0f) * 128.0f);
            b = min(max(b, 0), NB - 1);
            float eb = -8.0f + (float)b * 0.0078125f;     // exact (2^-7 grid)
            if (m < eb) b--;
            else if (m >= eb + 0.0078125f) b++;
            lo = bs[b]; hi = bs[b + 1];
        }
        while (lo < hi) {
            int mid = (lo + hi) >> 1;
            if (ts[mid] <= m) lo = mid + 1; else hi = mid;
        }
        sg[e] = (unsigned short)lo;
    }
    *(ushort4*)&g_seg[i0] = make_ushort4(sg[0], sg[1], sg[2], sg[3]);
}

// =============================================================================
// Kernel 3: Q/K/V projections. 32x64 tiles, 128 threads, thread 2x8, f32x2.
// =============================================================================
__device__ __forceinline__ void gemm32(const float* __restrict__ A, const float* __restrict__ W,
                                       const float* __restrict__ bias, float* __restrict__ C,
                                       int M, float scale) {
    __shared__ float As[16][36];
    __shared__ float Ws[16][68];
    int bm = blockIdx.y * 32;
    if (bm >= M) return;
    int bn = blockIdx.x * 64;
    int t = threadIdx.x;
    int ar = t & 31, ak = (t >> 5) * 4;
    int kw = t >> 3, nw = (t & 7) * 8;
    int ty = t >> 3, tx = t & 7;
    u64 acc2[2][4];
#pragma unroll
    for (int i = 0; i < 2; i++)
#pragma unroll
        for (int j = 0; j < 4; j++) acc2[i][j] = 0ull;
    for (int k0 = 0; k0 < DIMC; k0 += 16) {
        float4 a = *(const float4*)&A[(bm + ar) * DIMC + k0 + ak];
        float4 w0 = *(const float4*)&W[(k0 + kw) * DIMC + bn + nw];
        float4 w1 = *(const float4*)&W[(k0 + kw) * DIMC + bn + nw + 4];
        As[ak + 0][ar] = a.x; As[ak + 1][ar] = a.y;
        As[ak + 2][ar] = a.z; As[ak + 3][ar] = a.w;
        *(float4*)&Ws[kw][nw]     = w0;
        *(float4*)&Ws[kw][nw + 4] = w1;
        __syncthreads();
#pragma unroll
        for (int kk = 0; kk < 16; kk++) {
            float2 a2 = *(const float2*)&As[kk][ty * 2];
            ulonglong2 wp0 = *(const ulonglong2*)&Ws[kk][tx * 8];
            ulonglong2 wp1 = *(const ulonglong2*)&Ws[kk][tx * 8 + 4];
            u64 ax = pk2(a2.x, a2.x), ay = pk2(a2.y, a2.y);
            fma2(acc2[0][0], ax, wp0.x); fma2(acc2[0][1], ax, wp0.y);
            fma2(acc2[0][2], ax, wp1.x); fma2(acc2[0][3], ax, wp1.y);
            fma2(acc2[1][0], ay, wp0.x); fma2(acc2[1][1], ay, wp0.y);
            fma2(acc2[1][2], ay, wp1.x); fma2(acc2[1][3], ay, wp1.y);
        }
        __syncthreads();
    }
    float4 bsa = *(const float4*)&bias[bn + tx * 8];
    float4 bsb = *(const float4*)&bias[bn + tx * 8 + 4];
    float bs[8] = {bsa.x, bsa.y, bsa.z, bsa.w, bsb.x, bsb.y, bsb.z, bsb.w};
#pragma unroll
    for (int i = 0; i < 2; i++) {
        int row = bm + ty * 2 + i;
        float acc[8];
#pragma unroll
        for (int j = 0; j < 4; j++) {
            float2 p = up2(acc2[i][j]);
            acc[2 * j] = p.x; acc[2 * j + 1] = p.y;
        }
        float4 o0, o1;
        o0.x = (acc[0] + bs[0]) * scale; o0.y = (acc[1] + bs[1]) * scale;
        o0.z = (acc[2] + bs[2]) * scale; o0.w = (acc[3] + bs[3]) * scale;
        o1.x = (acc[4] + bs[4]) * scale; o1.y = (acc[5] + bs[5]) * scale;
        o1.z = (acc[6] + bs[6]) * scale; o1.w = (acc[7] + bs[7]) * scale;
        *(float4*)&C[row * DIMC + bn + tx * 8]     = o0;
        *(float4*)&C[row * DIMC + bn + tx * 8 + 4] = o1;
    }
}

__global__ void __launch_bounds__(128) gemm_qkv(
        const float* __restrict__ q_in, const float* __restrict__ k_in,
        const float* __restrict__ v_in,
        const float* __restrict__ Wq, const float* __restrict__ bq_,
        const float* __restrict__ Wk, const float* __restrict__ bk_,
        const float* __restrict__ Wv, const float* __restrict__ bv_) {
    const float *A, *W, *B; float *Cp; int M; float sc;
    if (blockIdx.z == 0)      { A = q_in; W = Wq; B = bq_; Cp = g_q; M = NQ; sc = 0.17677669529663687f; }
    else if (blockIdx.z == 1) { A = k_in; W = Wk; B = bk_; Cp = g_k; M = NK; sc = 1.0f; }
    else                      { A = v_in; W = Wv; B = bv_; Cp = g_v; M = NK; sc = 1.0f; }
    gemm32(A, W, B, Cp, M, sc);
}

// =============================================================================
// Kernel 4: FUSED attention, k-split x2.  256 threads, 2 blocks/SM (~105KB).
// =============================================================================
#define TQ      32
#define STSTR   36
#define KSTR    132
#define VSTR    36
#define OFF_ST  0
#define OFF_KV  (KSEG * STSTR)
#define OFF_Q   (OFF_KV + 128 * VSTR)
#define OFF_AC  (OFF_Q + 32 * 36)
#define OFF_PAD (OFF_AC + 2 * NSEG + 2)
#define OFF_PM  (OFF_PAD + KSEG)
#define OFF_PS  (OFF_PM + 256)
#define SMEM_FLOATS (OFF_PS + 256)
#define SMEM_BYTES  (SMEM_FLOATS * 4)

__global__ void __launch_bounds__(256, 2) fused_attn(const float* __restrict__ am,
                                                     const float* __restrict__ pad) {
    extern __shared__ float sm[];
    float*  ST   = sm + OFF_ST;
    float*  KV   = sm + OFF_KV;
    float*  Qs   = sm + OFF_Q;
    float2* AC   = (float2*)(sm + OFF_AC);
    float*  padp = sm + OFF_PAD;
    float*  pm   = sm + OFF_PM;
    float*  ps   = sm + OFF_PS;

    const int h    = blockIdx.y;
    const int bq   = blockIdx.x * TQ;
    const int ks   = blockIdx.z;
    const int kbase = ks * KSEG;
    const int t    = threadIdx.x;
    const int lane = t & 31, warp = t >> 5;

    // ---- prologue ----
    {
        int qr = t >> 3, d4 = (t & 7) * 4;
        float4 v = *(const float4*)&g_q[(bq + qr) * DIMC + h * HD + d4];
        Qs[(d4 + 0) * 36 + qr] = v.x; Qs[(d4 + 1) * 36 + qr] = v.y;
        Qs[(d4 + 2) * 36 + qr] = v.z; Qs[(d4 + 3) * 36 + qr] = v.w;
    }
    if (t < 128) {
        float4 p4 = *(const float4*)&pad[kbase + t * 4];
        float4 o; o.x = p4.x * -100.f; o.y = p4.y * -100.f; o.z = p4.z * -100.f; o.w = p4.w * -100.f;
        *(float4*)&padp[t * 4] = o;
    }
    for (int i = t; i < NSEG; i += 256)
        AC[i] = make_float2(g_A[h * NSEG + i], g_C[h * NSEG + i]);

    // ---- Phase A: 4 chunks of 128 k; thread tile 4k x 4q; XOR-swizzled Kt ----
    const int kr   = t >> 1;
    const int db   = (t & 1) * 16;
    const int kxor = kr ^ ((t & 1) << 4);
    const int tk4  = t >> 3;
    const int tq4  = t & 7;
    float* Kt = KV;

    float4 kv0, kv1, kv2, kv3;
    {
        const float* p = &g_k[(kbase + kr) * DIMC + h * HD + db];
        kv0 = *(const float4*)p;       kv1 = *(const float4*)(p + 4);
        kv2 = *(const float4*)(p + 8); kv3 = *(const float4*)(p + 12);
    }
    for (int c = 0; c < 4; c++) {
        __syncthreads();
        {
            float* B = Kt + db * KSTR + kxor;
            B[0 * KSTR] = kv0.x; B[1 * KSTR] = kv0.y; B[2 * KSTR] = kv0.z; B[3 * KSTR] = kv0.w;
            B[4 * KSTR] = kv1.x; B[5 * KSTR] = kv1.y; B[6 * KSTR] = kv1.z; B[7 * KSTR] = kv1.w;
            B[8 * KSTR] = kv2.x; B[9 * KSTR] = kv2.y; B[10* KSTR] = kv2.z; B[11* KSTR] = kv2.w;
            B[12* KSTR] = kv3.x; B[13* KSTR] = kv3.y; B[14* KSTR] = kv3.z; B[15* KSTR] = kv3.w;
        }
        __syncthreads();
        if (c < 3) {
            const float* p = &g_k[(kbase + (c + 1) * 128 + kr) * DIMC + h * HD + db];
            kv0 = *(const float4*)p;       kv1 = *(const float4*)(p + 4);
            kv2 = *(const float4*)(p + 8); kv3 = *(const float4*)(p + 12);
        }
        const int kg0 = c * 128 + tk4 * 4;
        const int gk0 = kbase + kg0;
        float4  m4[4];
        ushort4 s4[4];
#pragma unroll
        for (int j = 0; j < 4; j++) {
            int qg = bq + tq4 * 4 + j;
            m4[j] = *(const float4*)&am[qg * NK + gk0];
            s4[j] = *(const ushort4*)&g_seg[qg * NK + gk0];
        }
        u64 acc2[4][2];
#pragma unroll
        for (int i = 0; i < 4; i++) { acc2[i][0] = 0ull; acc2[i][1] = 0ull; }
#pragma unroll
        for (int d = 0; d < HD; d++) {
            float4 kb = *(const float4*)&Kt[d * KSTR + ((tk4 * 4) ^ ((d >> 4) << 4))];
            ulonglong2 qp = *(const ulonglong2*)&Qs[d * 36 + tq4 * 4];
            u64 kd0 = pk2(kb.x, kb.x), kd1 = pk2(kb.y, kb.y);
            u64 kd2 = pk2(kb.z, kb.z), kd3 = pk2(kb.w, kb.w);
            fma2(acc2[0][0], kd0, qp.x); fma2(acc2[0][1], kd0, qp.y);
            fma2(acc2[1][0], kd1, qp.x); fma2(acc2[1][1], kd1, qp.y);
            fma2(acc2[2][0], kd2, qp.x); fma2(acc2[2][1], kd2, qp.y);
            fma2(acc2[3][0], kd3, qp.x); fma2(acc2[3][1], kd3, qp.y);
        }
        float acc[4][4];
#pragma unroll
        for (int i = 0; i < 4; i++) {
            float2 p0 = up2(acc2[i][0]), p1 = up2(acc2[i][1]);
            acc[i][0] = p0.x; acc[i][1] = p0.y; acc[i][2] = p1.x; acc[i][3] = p1.y;
        }
#pragma unroll
        for (int j = 0; j < 4; j++) {
            float2 c0 = AC[s4[j].x], c1 = AC[s4[j].y], c2 = AC[s4[j].z], c3 = AC[s4[j].w];
            acc[0][j] += fmaf(c0.x, m4[j].x, c0.y);
            acc[1][j] += fmaf(c1.x, m4[j].y, c1.y);
            acc[2][j] += fmaf(c2.x, m4[j].z, c2.y);
            acc[3][j] += fmaf(c3.x, m4[j].w, c3.y);
        }
#pragma unroll
        for (int i = 0; i < 4; i++) {
            float pdv = padp[kg0 + i];
            float4 o;
            o.x = acc[i][0] + pdv; o.y = acc[i][1] + pdv;
            o.z = acc[i][2] + pdv; o.w = acc[i][3] + pdv;
            *(float4*)&ST[(kg0 + i) * STSTR + tq4 * 4] = o;
        }
    }
    __syncthreads();

    // ---- Phase B: partial softmax, float4-vectorized ----
    float4 gm4;
    {
        const int ki = lane >> 3;
        const int qu = (lane & 7) * 4;
        float* bp = ST + (warp * 64 + ki) * STSTR + qu;
        float4 mx4 = make_float4(-3.0e38f, -3.0e38f, -3.0e38f, -3.0e38f);
#pragma unroll
        for (int i = 0; i < 16; i++) {
            float4 v = *(const float4*)(bp + i * 4 * STSTR);
            mx4.x = fmaxf(mx4.x, v.x); mx4.y = fmaxf(mx4.y, v.y);
            mx4.z = fmaxf(mx4.z, v.z); mx4.w = fmaxf(mx4.w, v.w);
        }
#pragma unroll
        for (int o = 8; o <= 16; o <<= 1) {
            mx4.x = fmaxf(mx4.x, __shfl_xor_sync(0xffffffffu, mx4.x, o));
            mx4.y = fmaxf(mx4.y, __shfl_xor_sync(0xffffffffu, mx4.y, o));
            mx4.z = fmaxf(mx4.z, __shfl_xor_sync(0xffffffffu, mx4.z, o));
            mx4.w = fmaxf(mx4.w, __shfl_xor_sync(0xffffffffu, mx4.w, o));
        }
        if (lane < 8) *(float4*)&pm[warp * 32 + qu] = mx4;
        __syncthreads();
        gm4 = *(const float4*)&pm[qu];
#pragma unroll
        for (int j = 1; j < 8; j++) {
            float4 v = *(const float4*)&pm[j * 32 + qu];
            gm4.x = fmaxf(gm4.x, v.x); gm4.y = fmaxf(gm4.y, v.y);
            gm4.z = fmaxf(gm4.z, v.z); gm4.w = fmaxf(gm4.w, v.w);
        }
        float4 s4v = make_float4(0.f, 0.f, 0.f, 0.f);
#pragma unroll
        for (int i = 0; i < 16; i++) {
            float* p = bp + i * 4 * STSTR;
            float4 v = *(const float4*)p;
            v.x = __expf(v.x - gm4.x); v.y = __expf(v.y - gm4.y);
            v.z = __expf(v.z - gm4.z); v.w = __expf(v.w - gm4.w);
            *(float4*)p = v;
            s4v.x += v.x; s4v.y += v.y; s4v.z += v.z; s4v.w += v.w;
        }
#pragma unroll
        for (int o = 8; o <= 16; o <<= 1) {
            s4v.x += __shfl_xor_sync(0xffffffffu, s4v.x, o);
            s4v.y += __shfl_xor_sync(0xffffffffu, s4v.y, o);
            s4v.z += __shfl_xor_sync(0xffffffffu, s4v.z, o);
            s4v.w += __shfl_xor_sync(0xffffffffu, s4v.w, o);
        }
        if (lane < 8) *(float4*)&ps[warp * 32 + qu] = s4v;
        __syncthreads();
        if (warp == 0 && lane < 8) {
            float4 t4 = *(const float4*)&ps[qu];
#pragma unroll
            for (int j = 1; j < 8; j++) {
                float4 v = *(const float4*)&ps[j * 32 + qu];
                t4.x += v.x; t4.y += v.y; t4.z += v.z; t4.w += v.w;
            }
            int base = ks * NH * NQ + h * NQ + bq;
            *(float4*)&g_pm[base + qu] = gm4;
            *(float4*)&g_ps[base + qu] = t4;
        }
    }

    // ---- Phase C: O_part = P_unnorm @ V ----
    const int vkr = t >> 1;
    const int vdh = (t & 1) * 16;
    {
        const float* p = &g_v[(kbase + vkr) * DIMC + h * HD + vdh];
        kv0 = *(const float4*)p;       kv1 = *(const float4*)(p + 4);
        kv2 = *(const float4*)(p + 8); kv3 = *(const float4*)(p + 12);
        float* B = KV + vkr * VSTR + vdh;
        *(float4*)B = kv0; *(float4*)(B + 4) = kv1;
        *(float4*)(B + 8) = kv2; *(float4*)(B + 12) = kv3;
    }
    __syncthreads();

    const int g    = t & 7;
    const int tile = t >> 3;
    const int q0   = (tile >> 2) * 4;
    const int d0   = (tile & 3) * 8;
    u64 acc2[4][4];
#pragma unroll
    for (int qi = 0; qi < 4; qi++)
#pragma unroll
        for (int j = 0; j < 4; j++) acc2[qi][j] = 0ull;
    for (int c = 0; c < 4; c++) {
        if (c < 3) {
            const float* p = &g_v[(kbase + (c + 1) * 128 + vkr) * DIMC + h * HD + vdh];
            kv0 = *(const float4*)p;       kv1 = *(const float4*)(p + 4);
            kv2 = *(const float4*)(p + 8); kv3 = *(const float4*)(p + 12);
        }
        const float* Vb = KV;
#pragma unroll
        for (int i = 0; i < 16; i++) {
            int kl = i * 8 + g;
            int kg = c * 128 + kl;
            float4 pA = *(const float4*)&ST[kg * STSTR + q0];
            ulonglong2 vA = *(const ulonglong2*)&Vb[kl * VSTR + d0];
            ulonglong2 vB = *(const ulonglong2*)&Vb[kl * VSTR + d0 + 4];
            u64 vp[4] = {vA.x, vA.y, vB.x, vB.y};
            u64 pd0 = pk2(pA.x, pA.x), pd1 = pk2(pA.y, pA.y);
            u64 pd2 = pk2(pA.z, pA.z), pd3 = pk2(pA.w, pA.w);
#pragma unroll
            for (int j = 0; j < 4; j++) {
                fma2(acc2[0][j], pd0, vp[j]);
                fma2(acc2[1][j], pd1, vp[j]);
                fma2(acc2[2][j], pd2, vp[j]);
                fma2(acc2[3][j], pd3, vp[j]);
            }
        }
        __syncthreads();
        if (c < 3) {
            float* B = KV + vkr * VSTR + vdh;
            *(float4*)B = kv0; *(float4*)(B + 4) = kv1;
            *(float4*)(B + 8) = kv2; *(float4*)(B + 12) = kv3;
            __syncthreads();
        }
    }

#pragma unroll
    for (int o = 1; o < 8; o <<= 1)
#pragma unroll
        for (int qi = 0; qi < 4; qi++)
#pragma unroll
            for (int j = 0; j < 4; j++) {
                u64 other = __shfl_xor_sync(0xffffffffu, acc2[qi][j], o);
                float2 a = up2(acc2[qi][j]), b = up2(other);
                acc2[qi][j] = pk2(a.x + b.x, a.y + b.y);
            }

    if (g == 0) {
#pragma unroll
        for (int qi = 0; qi < 4; qi++) {
            int q = q0 + qi;
            float2 p0 = up2(acc2[qi][0]), p1 = up2(acc2[qi][1]);
            float2 p2 = up2(acc2[qi][2]), p3 = up2(acc2[qi][3]);
            float4 oA, oB;
            oA.x = p0.x; oA.y = p0.y; oA.z = p1.x; oA.w = p1.y;
            oB.x = p2.x; oB.y = p2.y; oB.z = p3.x; oB.w = p3.y;
            float* op = &g_pO[ks * NQ * DIMC + (bq + q) * DIMC + h * HD + d0];
            *(float4*)op = oA; *(float4*)(op + 4) = oB;
        }
    }
}

// =============================================================================
// Kernel 5: output projection with split-combine folded into A-load.
// =============================================================================
__global__ void __launch_bounds__(128) gemm_final(
        const float* __restrict__ Wp, const float* __restrict__ bp_,
        float* __restrict__ out) {
    __shared__ float As[16][20];
    __shared__ float Ws[16][68];
    __shared__ float cw[16 * NH * 2];
    const int bm = blockIdx.y * 16;
    const int bn = blockIdx.x * 64;
    const int t  = threadIdx.x;

    {
        int q = t >> 3, hh = t & 7;
        int i1 = hh * NQ + bm + q;
        float m1 = g_pm[i1], m2 = g_pm[NH * NQ + i1];
        float s1 = g_ps[i1], s2 = g_ps[NH * NQ + i1];
        float M = fmaxf(m1, m2);
        float w1 = __expf(m1 - M), w2 = __expf(m2 - M);
        float inv = 1.0f / (w1 * s1 + w2 * s2);
        cw[(q * NH + hh) * 2]     = w1 * inv;
        cw[(q * NH + hh) * 2 + 1] = w2 * inv;
    }
    __syncthreads();

    const int ra = t >> 2, ka = (t & 3) * 4;
    const int kw = t >> 3, nw = (t & 7) * 8;
    const int ty = t >> 4, tx = t & 15;
    u64 acc2[2][2] = {{0ull, 0ull}, {0ull, 0ull}};
    for (int k0 = 0; k0 < DIMC; k0 += 16) {
        if (t < 64) {
            int c = k0 + ka;
            int hh = c >> 5;
            float4 o1 = *(const float4*)&g_pO[(bm + ra) * DIMC + c];
            float4 o2 = *(const float4*)&g_pO[NQ * DIMC + (bm + ra) * DIMC + c];
            float w1 = cw[(ra * NH + hh) * 2], w2 = cw[(ra * NH + hh) * 2 + 1];
            As[ka + 0][ra] = w1 * o1.x + w2 * o2.x;
            As[ka + 1][ra] = w1 * o1.y + w2 * o2.y;
            As[ka + 2][ra] = w1 * o1.z + w2 * o2.z;
            As[ka + 3][ra] = w1 * o1.w + w2 * o2.w;
        }
        *(float4*)&Ws[kw][nw]     = *(const float4*)&Wp[(k0 + kw) * DIMC + bn + nw];
        *(float4*)&Ws[kw][nw + 4] = *(const float4*)&Wp[(k0 + kw) * DIMC + bn + nw + 4];
        __syncthreads();
#pragma unroll
        for (int kk = 0; kk < 16; kk++) {
            float2 a2 = *(const float2*)&As[kk][ty * 2];
            ulonglong2 wp = *(const ulonglong2*)&Ws[kk][tx * 4];
            u64 ax = pk2(a2.x, a2.x), ay = pk2(a2.y, a2.y);
            fma2(acc2[0][0], ax, wp.x); fma2(acc2[0][1], ax, wp.y);
            fma2(acc2[1][0], ay, wp.x); fma2(acc2[1][1], ay, wp.y);
        }
        __syncthreads();
    }
    float4 bb = *(const float4*)&bp_[bn + tx * 4];
#pragma unroll
    for (int i = 0; i < 2; i++) {
        float2 p0 = up2(acc2[i][0]), p1 = up2(acc2[i][1]);
        float4 o;
        o.x = p0.x + bb.x; o.y = p0.y + bb.y;
        o.z = p1.x + bb.z; o.w = p1.y + bb.w;
        *(float4*)&out[(bm + ty * 2 + i) * DIMC + bn + tx * 4] = o;
    }
}

// =============================================================================
extern "C" void kernel_launch(void* const* d_in, const int* in_sizes, int n_in,
                              void* d_out, int out_size) {
    const float* query = (const float*)d_in[0];
    const float* kin   = (const float*)d_in[1];
    const float* vin   = (const float*)d_in[2];
    const float* pad   = (const float*)d_in[3];
    const float* am    = (const float*)d_in[4];
    const float* Wq    = (const float*)d_in[5];
    const float* bq    = (const float*)d_in[6];
    const float* Wk    = (const float*)d_in[7];
    const float* bk    = (const float*)d_in[8];
    const float* Wv    = (const float*)d_in[9];
    const float* bv    = (const float*)d_in[10];
    const float* Wp    = (const float*)d_in[11];
    const float* bp    = (const float*)d_in[12];
    const float* W1    = (const float*)d_in[13];
    const float* b1    = (const float*)d_in[14];
    const float* W2    = (const float*)d_in[15];
    float* out = (float*)d_out;

    cudaFuncSetAttribute(fused_attn, cudaFuncAttributeMaxDynamicSharedMemorySize, SMEM_BYTES);

    pwl_build<<<1, 512>>>(W1, b1, W2);
    seg_kernel<<<NQ * NK / 1024, 256>>>(am);
    gemm_qkv<<<dim3(4, 32, 3), 128>>>(query, kin, vin, Wq, bq, Wk, bk, Wv, bv);
    fused_attn<<<dim3(16, 8, 2), 256, SMEM_BYTES>>>(am, pad);
    gemm_final<<<dim3(4, 32), 128>>>(Wp, bp, out);
}

// round 10
// speedup vs baseline: 1.2388x; 1.2388x over previous
#include <cuda_runtime.h>

#define NQ   512
#define NK   1024
#define DIMC 256
#define NH   8
#define HD   32
#define RPE  512
#define NSEG (RPE + 1)
#define KSEG 512
#define SPLIT 2
#define NB   2048

typedef unsigned long long u64;

// ---- packed f32x2 helpers (Blackwell) ----
__device__ __forceinline__ u64 pk2(float lo, float hi) {
    u64 r; asm("mov.b64 %0, {%1, %2};" : "=l"(r) : "f"(lo), "f"(hi)); return r;
}
__device__ __forceinline__ void fma2(u64& d, u64 a, u64 b) {
    asm("fma.rn.f32x2 %0, %1, %2, %0;" : "+l"(d) : "l"(a), "l"(b));
}
__device__ __forceinline__ float2 up2(u64 d) {
    float2 f; asm("mov.b64 {%0, %1}, %2;" : "=f"(f.x), "=f"(f.y) : "l"(d)); return f;
}

// ---------------- scratch ----------------
static __device__ float          g_tsort[RPE];
static __device__ unsigned short g_bstart[NB + 1];
static __device__ float          g_A[NH * NSEG];
static __device__ float          g_C[NH * NSEG];
static __device__ unsigned short g_seg[NQ * NK];
static __device__ float          g_q[NQ * DIMC];
static __device__ float          g_k[NK * DIMC];
static __device__ float          g_v[NK * DIMC];
static __device__ float          g_pO[SPLIT * NQ * DIMC];
static __device__ float          g_pm[SPLIT * NH * NQ];
static __device__ float          g_ps[SPLIT * NH * NQ];

// =============================================================================
// Kernel 1: PWL CPB bias tables (rank-sort) + bucket LUT for fast seg lookup.
// =============================================================================
__global__ void pwl_build(const float* __restrict__ W1, const float* __restrict__ b1,
                          const float* __restrict__ W2) {
    __shared__ float key[RPE];
    __shared__ float skey[RPE];
    __shared__ int   sidx[RPE];
    __shared__ float sW1[RPE], sb1[RPE];
    __shared__ float sW2[RPE * NH];

    const int tid = threadIdx.x;
    float w = W1[tid], b = b1[tid];
    float t;
    if (w != 0.0f) t = -b / w;
    else t = (b > 0.0f) ? -__int_as_float(0x7f800000) : __int_as_float(0x7f800000);
    key[tid] = t;
    sW1[tid] = w;
    sb1[tid] = b;
#pragma unroll
    for (int h = 0; h < NH; h++) sW2[tid * NH + h] = W2[tid * NH + h];
    __syncthreads();

    int rank = 0;
    float ki = t;
#pragma unroll 4
    for (int j4 = 0; j4 < RPE / 4; j4++) {
        float4 kj = *(const float4*)&key[j4 * 4];
        int j = j4 * 4;
        rank += (kj.x < ki) || (kj.x == ki && (j + 0) < tid);
        rank += (kj.y < ki) || (kj.y == ki && (j + 1) < tid);
        rank += (kj.z < ki) || (kj.z == ki && (j + 2) < tid);
        rank += (kj.w < ki) || (kj.w == ki && (j + 3) < tid);
    }
    skey[rank] = ki;
    sidx[rank] = tid;
    __syncthreads();
    g_tsort[tid] = skey[tid];

    // ---- bucket LUT: g_bstart[b] = #breakpoints < (-8 + b/128) ----
#pragma unroll
    for (int b4 = 0; b4 < 4; b4++) {
        int bb = tid * 4 + b4;
        float edge = -8.0f + (float)bb * 0.0078125f;
        int lo = 0, hi = RPE;
        while (lo < hi) {
            int mid = (lo + hi) >> 1;
            if (skey[mid] < edge) lo = mid + 1; else hi = mid;
        }
        g_bstart[bb] = (unsigned short)lo;
    }
    if (tid == 0) {
        float edge = 8.0f;
        int lo = 0, hi = RPE;
        while (lo < hi) {
            int mid = (lo + hi) >> 1;
            if (skey[mid] < edge) lo = mid + 1; else hi = mid;
        }
        g_bstart[NB] = (unsigned short)lo;
    }

    const int warp = tid >> 5, lane = tid & 31;
    if (warp < NH) {
        const int h = warp;
        float eA[16], eC[16];
        float leA = 0.f, leC = 0.f, mA = 0.f, mC = 0.f;
#pragma unroll
        for (int pp = 0; pp < 16; pp++) {
            int p = lane * 16 + pp;
            int r = sidx[p];
            float w1 = sW1[r], bb = sb1[r], w2 = sW2[r * NH + h];
            float ca, cc; bool plus;
            if (w1 > 0.f)      { plus = true;  ca = w1 * w2; cc = bb * w2; }
            else if (w1 < 0.f) { plus = false; ca = w1 * w2; cc = bb * w2; }
            else               { plus = true;  ca = 0.f;     cc = (bb > 0.f) ? bb * w2 : 0.f; }
            float ea = plus ? ca : -ca;
            float ec = plus ? cc : -cc;
            eA[pp] = ea; eC[pp] = ec;
            leA += ea; leC += ec;
            if (!plus) { mA += ca; mC += cc; }
        }
        float inA = leA, inC = leC;
#pragma unroll
        for (int o = 1; o < 32; o <<= 1) {
            float ta = __shfl_up_sync(0xffffffffu, inA, o);
            float tc = __shfl_up_sync(0xffffffffu, inC, o);
            if (lane >= o) { inA += ta; inC += tc; }
        }
        float exA = inA - leA, exC = inC - leC;
#pragma unroll
        for (int o = 16; o > 0; o >>= 1) {
            mA += __shfl_xor_sync(0xffffffffu, mA, o);
            mC += __shfl_xor_sync(0xffffffffu, mC, o);
        }
        if (lane == 0) { g_A[h * NSEG] = mA; g_C[h * NSEG] = mC; }
        float runA = exA, runC = exC;
#pragma unroll
        for (int pp = 0; pp < 16; pp++) {
            runA += eA[pp]; runC += eC[pp];
            int s = lane * 16 + pp + 1;
            g_A[h * NSEG + s] = mA + runA;
            g_C[h * NSEG + s] = mC + runC;
        }
    }
}

// =============================================================================
// Kernel 2: segment index per (q,k) — bucket LUT narrows search to ~0-1 steps.
// =============================================================================
__global__ void seg_kernel(const float* __restrict__ am) {
    __shared__ float ts[RPE];
    __shared__ unsigned short bs[NB + 4];
    int t = threadIdx.x;
    ts[t] = g_tsort[t];
    ts[t + 256] = g_tsort[t + 256];
    for (int i = t; i < NB + 1; i += 256) bs[i] = g_bstart[i];
    __syncthreads();
    int i0 = (blockIdx.x * 256 + t) * 4;
    float4 m4 = *(const float4*)&am[i0];
    float mv[4] = {m4.x, m4.y, m4.z, m4.w};
    unsigned short sg[4];
#pragma unroll
    for (int e = 0; e < 4; e++) {
        float m = mv[e];
        int lo, hi;
        if (m < -8.0f)      { lo = 0;      hi = bs[0]; }
        else if (m >= 8.0f) { lo = bs[NB]; hi = RPE; }
        else {
            int b = (int)((m + 8.0f) * 128.0f);
            b = min(max(b, 0), NB - 1);
            float eb = -8.0f + (float)b * 0.0078125f;
            if (m < eb) b--;
            else if (m >= eb + 0.0078125f) b++;
            lo = bs[b]; hi = bs[b + 1];
        }
        while (lo < hi) {
            int mid = (lo + hi) >> 1;
            if (ts[mid] <= m) lo = mid + 1; else hi = mid;
        }
        sg[e] = (unsigned short)lo;
    }
    *(ushort4*)&g_seg[i0] = make_ushort4(sg[0], sg[1], sg[2], sg[3]);
}

// =============================================================================
// Kernel 3: Q/K/V projections. 32x64 tiles, 128 threads, thread 2x8, f32x2.
// =============================================================================
__device__ __forceinline__ void gemm32(const float* __restrict__ A, const float* __restrict__ W,
                                       const float* __restrict__ bias, float* __restrict__ C,
                                       int M, float scale) {
    __shared__ float As[16][36];
    __shared__ float Ws[16][68];
    int bm = blockIdx.y * 32;
    if (bm >= M) return;
    int bn = blockIdx.x * 64;
    int t = threadIdx.x;
    int ar = t & 31, ak = (t >> 5) * 4;
    int kw = t >> 3, nw = (t & 7) * 8;
    int ty = t >> 3, tx = t & 7;
    u64 acc2[2][4];
#pragma unroll
    for (int i = 0; i < 2; i++)
#pragma unroll
        for (int j = 0; j < 4; j++) acc2[i][j] = 0ull;
    for (int k0 = 0; k0 < DIMC; k0 += 16) {
        float4 a = *(const float4*)&A[(bm + ar) * DIMC + k0 + ak];
        float4 w0 = *(const float4*)&W[(k0 + kw) * DIMC + bn + nw];
        float4 w1 = *(const float4*)&W[(k0 + kw) * DIMC + bn + nw + 4];
        As[ak + 0][ar] = a.x; As[ak + 1][ar] = a.y;
        As[ak + 2][ar] = a.z; As[ak + 3][ar] = a.w;
        *(float4*)&Ws[kw][nw]     = w0;
        *(float4*)&Ws[kw][nw + 4] = w1;
        __syncthreads();
#pragma unroll
        for (int kk = 0; kk < 16; kk++) {
            float2 a2 = *(const float2*)&As[kk][ty * 2];
            ulonglong2 wp0 = *(const ulonglong2*)&Ws[kk][tx * 8];
            ulonglong2 wp1 = *(const ulonglong2*)&Ws[kk][tx * 8 + 4];
            u64 ax = pk2(a2.x, a2.x), ay = pk2(a2.y, a2.y);
            fma2(acc2[0][0], ax, wp0.x); fma2(acc2[0][1], ax, wp0.y);
            fma2(acc2[0][2], ax, wp1.x); fma2(acc2[0][3], ax, wp1.y);
            fma2(acc2[1][0], ay, wp0.x); fma2(acc2[1][1], ay, wp0.y);
            fma2(acc2[1][2], ay, wp1.x); fma2(acc2[1][3], ay, wp1.y);
        }
        __syncthreads();
    }
    float4 bsa = *(const float4*)&bias[bn + tx * 8];
    float4 bsb = *(const float4*)&bias[bn + tx * 8 + 4];
    float bs[8] = {bsa.x, bsa.y, bsa.z, bsa.w, bsb.x, bsb.y, bsb.z, bsb.w};
#pragma unroll
    for (int i = 0; i < 2; i++) {
        int row = bm + ty * 2 + i;
        float acc[8];
#pragma unroll
        for (int j = 0; j < 4; j++) {
            float2 p = up2(acc2[i][j]);
            acc[2 * j] = p.x; acc[2 * j + 1] = p.y;
        }
        float4 o0, o1;
        o0.x = (acc[0] + bs[0]) * scale; o0.y = (acc[1] + bs[1]) * scale;
        o0.z = (acc[2] + bs[2]) * scale; o0.w = (acc[3] + bs[3]) * scale;
        o1.x = (acc[4] + bs[4]) * scale; o1.y = (acc[5] + bs[5]) * scale;
        o1.z = (acc[6] + bs[6]) * scale; o1.w = (acc[7] + bs[7]) * scale;
        *(float4*)&C[row * DIMC + bn + tx * 8]     = o0;
        *(float4*)&C[row * DIMC + bn + tx * 8 + 4] = o1;
    }
}

__global__ void __launch_bounds__(128) gemm_qkv(
        const float* __restrict__ q_in, const float* __restrict__ k_in,
        const float* __restrict__ v_in,
        const float* __restrict__ Wq, const float* __restrict__ bq_,
        const float* __restrict__ Wk, const float* __restrict__ bk_,
        const float* __restrict__ Wv, const float* __restrict__ bv_) {
    const float *A, *W, *B; float *Cp; int M; float sc;
    if (blockIdx.z == 0)      { A = q_in; W = Wq; B = bq_; Cp = g_q; M = NQ; sc = 0.17677669529663687f; }
    else if (blockIdx.z == 1) { A = k_in; W = Wk; B = bk_; Cp = g_k; M = NK; sc = 1.0f; }
    else                      { A = v_in; W = Wv; B = bv_; Cp = g_v; M = NK; sc = 1.0f; }
    gemm32(A, W, B, Cp, M, sc);
}

// =============================================================================
// Kernel 4: FUSED attention, k-split x2.  256 threads, 2 blocks/SM (~105KB).
// =============================================================================
#define TQ      32
#define STSTR   36
#define KSTR    132
#define VSTR    36
#define OFF_ST  0
#define OFF_KV  (KSEG * STSTR)
#define OFF_Q   (OFF_KV + 128 * VSTR)
#define OFF_AC  (OFF_Q + 32 * 36)
#define OFF_PAD (OFF_AC + 2 * NSEG + 2)
#define OFF_PM  (OFF_PAD + KSEG)
#define OFF_PS  (OFF_PM + 256)
#define SMEM_FLOATS (OFF_PS + 256)
#define SMEM_BYTES  (SMEM_FLOATS * 4)

__global__ void __launch_bounds__(256, 2) fused_attn(const float* __restrict__ am,
                                                     const float* __restrict__ pad) {
    extern __shared__ float sm[];
    float*  ST   = sm + OFF_ST;
    float*  KV   = sm + OFF_KV;
    float*  Qs   = sm + OFF_Q;
    float2* AC   = (float2*)(sm + OFF_AC);
    float*  padp = sm + OFF_PAD;
    float*  pm   = sm + OFF_PM;
    float*  ps   = sm + OFF_PS;

    const int h    = blockIdx.y;
    const int bq   = blockIdx.x * TQ;
    const int ks   = blockIdx.z;
    const int kbase = ks * KSEG;
    const int t    = threadIdx.x;
    const int lane = t & 31, warp = t >> 5;

    // ---- prologue ----
    {
        int qr = t >> 3, d4 = (t & 7) * 4;
        float4 v = *(const float4*)&g_q[(bq + qr) * DIMC + h * HD + d4];
        Qs[(d4 + 0) * 36 + qr] = v.x; Qs[(d4 + 1) * 36 + qr] = v.y;
        Qs[(d4 + 2) * 36 + qr] = v.z; Qs[(d4 + 3) * 36 + qr] = v.w;
    }
    if (t < 128) {
        float4 p4 = *(const float4*)&pad[kbase + t * 4];
        float4 o; o.x = p4.x * -100.f; o.y = p4.y * -100.f; o.z = p4.z * -100.f; o.w = p4.w * -100.f;
        *(float4*)&padp[t * 4] = o;
    }
    for (int i = t; i < NSEG; i += 256)
        AC[i] = make_float2(g_A[h * NSEG + i], g_C[h * NSEG + i]);

    // ---- Phase A: 4 chunks of 128 k; thread tile 4k x 4q; XOR-swizzled Kt ----
    const int kr   = t >> 1;
    const int db   = (t & 1) * 16;
    const int kxor = kr ^ ((t & 1) << 4);
    const int tk4  = t >> 3;
    const int tq4  = t & 7;
    float* Kt = KV;

    float4 kv0, kv1, kv2, kv3;
    {
        const float* p = &g_k[(kbase + kr) * DIMC + h * HD + db];
        kv0 = *(const float4*)p;       kv1 = *(const float4*)(p + 4);
        kv2 = *(const float4*)(p + 8); kv3 = *(const float4*)(p + 12);
    }
    for (int c = 0; c < 4; c++) {
        __syncthreads();
        {
            float* B = Kt + db * KSTR + kxor;
            B[0 * KSTR] = kv0.x; B[1 * KSTR] = kv0.y; B[2 * KSTR] = kv0.z; B[3 * KSTR] = kv0.w;
            B[4 * KSTR] = kv1.x; B[5 * KSTR] = kv1.y; B[6 * KSTR] = kv1.z; B[7 * KSTR] = kv1.w;
            B[8 * KSTR] = kv2.x; B[9 * KSTR] = kv2.y; B[10* KSTR] = kv2.z; B[11* KSTR] = kv2.w;
            B[12* KSTR] = kv3.x; B[13* KSTR] = kv3.y; B[14* KSTR] = kv3.z; B[15* KSTR] = kv3.w;
        }
        __syncthreads();
        if (c < 3) {
            const float* p = &g_k[(kbase + (c + 1) * 128 + kr) * DIMC + h * HD + db];
            kv0 = *(const float4*)p;       kv1 = *(const float4*)(p + 4);
            kv2 = *(const float4*)(p + 8); kv3 = *(const float4*)(p + 12);
        }
        const int kg0 = c * 128 + tk4 * 4;
        const int gk0 = kbase + kg0;
        float4  m4[4];
        ushort4 s4[4];
#pragma unroll
        for (int j = 0; j < 4; j++) {
            int qg = bq + tq4 * 4 + j;
            m4[j] = *(const float4*)&am[qg * NK + gk0];
            s4[j] = *(const ushort4*)&g_seg[qg * NK + gk0];
        }
        u64 acc2[4][2];
#pragma unroll
        for (int i = 0; i < 4; i++) { acc2[i][0] = 0ull; acc2[i][1] = 0ull; }
#pragma unroll
        for (int d = 0; d < HD; d++) {
            float4 kb = *(const float4*)&Kt[d * KSTR + ((tk4 * 4) ^ ((d >> 4) << 4))];
            ulonglong2 qp = *(const ulonglong2*)&Qs[d * 36 + tq4 * 4];
            u64 kd0 = pk2(kb.x, kb.x), kd1 = pk2(kb.y, kb.y);
            u64 kd2 = pk2(kb.z, kb.z), kd3 = pk2(kb.w, kb.w);
            fma2(acc2[0][0], kd0, qp.x); fma2(acc2[0][1], kd0, qp.y);
            fma2(acc2[1][0], kd1, qp.x); fma2(acc2[1][1], kd1, qp.y);
            fma2(acc2[2][0], kd2, qp.x); fma2(acc2[2][1], kd2, qp.y);
            fma2(acc2[3][0], kd3, qp.x); fma2(acc2[3][1], kd3, qp.y);
        }
        float acc[4][4];
#pragma unroll
        for (int i = 0; i < 4; i++) {
            float2 p0 = up2(acc2[i][0]), p1 = up2(acc2[i][1]);
            acc[i][0] = p0.x; acc[i][1] = p0.y; acc[i][2] = p1.x; acc[i][3] = p1.y;
        }
#pragma unroll
        for (int j = 0; j < 4; j++) {
            float2 c0 = AC[s4[j].x], c1 = AC[s4[j].y], c2 = AC[s4[j].z], c3 = AC[s4[j].w];
            acc[0][j] += fmaf(c0.x, m4[j].x, c0.y);
            acc[1][j] += fmaf(c1.x, m4[j].y, c1.y);
            acc[2][j] += fmaf(c2.x, m4[j].z, c2.y);
            acc[3][j] += fmaf(c3.x, m4[j].w, c3.y);
        }
#pragma unroll
        for (int i = 0; i < 4; i++) {
            float pdv = padp[kg0 + i];
            float4 o;
            o.x = acc[i][0] + pdv; o.y = acc[i][1] + pdv;
            o.z = acc[i][2] + pdv; o.w = acc[i][3] + pdv;
            *(float4*)&ST[(kg0 + i) * STSTR + tq4 * 4] = o;
        }
    }
    __syncthreads();

    // ---- Phase B: partial softmax, float4-vectorized ----
    float4 gm4;
    {
        const int ki = lane >> 3;
        const int qu = (lane & 7) * 4;
        float* bp = ST + (warp * 64 + ki) * STSTR + qu;
        float4 mx4 = make_float4(-3.0e38f, -3.0e38f, -3.0e38f, -3.0e38f);
#pragma unroll
        for (int i = 0; i < 16; i++) {
            float4 v = *(const float4*)(bp + i * 4 * STSTR);
            mx4.x = fmaxf(mx4.x, v.x); mx4.y = fmaxf(mx4.y, v.y);
            mx4.z = fmaxf(mx4.z, v.z); mx4.w = fmaxf(mx4.w, v.w);
        }
#pragma unroll
        for (int o = 8; o <= 16; o <<= 1) {
            mx4.x = fmaxf(mx4.x, __shfl_xor_sync(0xffffffffu, mx4.x, o));
            mx4.y = fmaxf(mx4.y, __shfl_xor_sync(0xffffffffu, mx4.y, o));
            mx4.z = fmaxf(mx4.z, __shfl_xor_sync(0xffffffffu, mx4.z, o));
            mx4.w = fmaxf(mx4.w, __shfl_xor_sync(0xffffffffu, mx4.w, o));
        }
        if (lane < 8) *(float4*)&pm[warp * 32 + qu] = mx4;
        __syncthreads();
        gm4 = *(const float4*)&pm[qu];
#pragma unroll
        for (int j = 1; j < 8; j++) {
            float4 v = *(const float4*)&pm[j * 32 + qu];
            gm4.x = fmaxf(gm4.x, v.x); gm4.y = fmaxf(gm4.y, v.y);
            gm4.z = fmaxf(gm4.z, v.z); gm4.w = fmaxf(gm4.w, v.w);
        }
        float4 s4v = make_float4(0.f, 0.f, 0.f, 0.f);
#pragma unroll
        for (int i = 0; i < 16; i++) {
            float* p = bp + i * 4 * STSTR;
            float4 v = *(const float4*)p;
            v.x = __expf(v.x - gm4.x); v.y = __expf(v.y - gm4.y);
            v.z = __expf(v.z - gm4.z); v.w = __expf(v.w - gm4.w);
            *(float4*)p = v;
            s4v.x += v.x; s4v.y += v.y; s4v.z += v.z; s4v.w += v.w;
        }
#pragma unroll
        for (int o = 8; o <= 16; o <<= 1) {
            s4v.x += __shfl_xor_sync(0xffffffffu, s4v.x, o);
            s4v.y += __shfl_xor_sync(0xffffffffu, s4v.y, o);
            s4v.z += __shfl_xor_sync(0xffffffffu, s4v.z, o);
            s4v.w += __shfl_xor_sync(0xffffffffu, s4v.w, o);
        }
        if (lane < 8) *(float4*)&ps[warp * 32 + qu] = s4v;
        __syncthreads();
        if (warp == 0 && lane < 8) {
            float4 t4 = *(const float4*)&ps[qu];
#pragma unroll
            for (int j = 1; j < 8; j++) {
                float4 v = *(const float4*)&ps[j * 32 + qu];
                t4.x += v.x; t4.y += v.y; t4.z += v.z; t4.w += v.w;
            }
            int base = ks * NH * NQ + h * NQ + bq;
            *(float4*)&g_pm[base + qu] = gm4;
            *(float4*)&g_ps[base + qu] = t4;
        }
    }

    // ---- Phase C: O_part = P_unnorm @ V ----
    const int vkr = t >> 1;
    const int vdh = (t & 1) * 16;
    {
        const float* p = &g_v[(kbase + vkr) * DIMC + h * HD + vdh];
        kv0 = *(const float4*)p;       kv1 = *(const float4*)(p + 4);
        kv2 = *(const float4*)(p + 8); kv3 = *(const float4*)(p + 12);
        float* B = KV + vkr * VSTR + vdh;
        *(float4*)B = kv0; *(float4*)(B + 4) = kv1;
        *(float4*)(B + 8) = kv2; *(float4*)(B + 12) = kv3;
    }
    __syncthreads();

    const int g    = t & 7;
    const int tile = t >> 3;
    const int q0   = (tile >> 2) * 4;
    const int d0   = (tile & 3) * 8;
    u64 acc2[4][4];
#pragma unroll
    for (int qi = 0; qi < 4; qi++)
#pragma unroll
        for (int j = 0; j < 4; j++) acc2[qi][j] = 0ull;
    for (int c = 0; c < 4; c++) {
        if (c < 3) {
            const float* p = &g_v[(kbase + (c + 1) * 128 + vkr) * DIMC + h * HD + vdh];
            kv0 = *(const float4*)p;       kv1 = *(const float4*)(p + 4);
            kv2 = *(const float4*)(p + 8); kv3 = *(const float4*)(p + 12);
        }
        const float* Vb = KV;
#pragma unroll
        for (int i = 0; i < 16; i++) {
            int kl = i * 8 + g;
            int kg = c * 128 + kl;
            float4 pA = *(const float4*)&ST[kg * STSTR + q0];
            ulonglong2 vA = *(const ulonglong2*)&Vb[kl * VSTR + d0];
            ulonglong2 vB = *(const ulonglong2*)&Vb[kl * VSTR + d0 + 4];
            u64 vp[4] = {vA.x, vA.y, vB.x, vB.y};
            u64 pd0 = pk2(pA.x, pA.x), pd1 = pk2(pA.y, pA.y);
            u64 pd2 = pk2(pA.z, pA.z), pd3 = pk2(pA.w, pA.w);
#pragma unroll
            for (int j = 0; j < 4; j++) {
                fma2(acc2[0][j], pd0, vp[j]);
                fma2(acc2[1][j], pd1, vp[j]);
                fma2(acc2[2][j], pd2, vp[j]);
                fma2(acc2[3][j], pd3, vp[j]);
            }
        }
        __syncthreads();
        if (c < 3) {
            float* B = KV + vkr * VSTR + vdh;
            *(float4*)B = kv0; *(float4*)(B + 4) = kv1;
            *(float4*)(B + 8) = kv2; *(float4*)(B + 12) = kv3;
            __syncthreads();
        }
    }

#pragma unroll
    for (int o = 1; o < 8; o <<= 1)
#pragma unroll
        for (int qi = 0; qi < 4; qi++)
#pragma unroll
            for (int j = 0; j < 4; j++) {
                u64 other = __shfl_xor_sync(0xffffffffu, acc2[qi][j], o);
                float2 a = up2(acc2[qi][j]), b = up2(other);
                acc2[qi][j] = pk2(a.x + b.x, a.y + b.y);
            }

    if (g == 0) {
#pragma unroll
        for (int qi = 0; qi < 4; qi++) {
            int q = q0 + qi;
            float2 p0 = up2(acc2[qi][0]), p1 = up2(acc2[qi][1]);
            float2 p2 = up2(acc2[qi][2]), p3 = up2(acc2[qi][3]);
            float4 oA, oB;
            oA.x = p0.x; oA.y = p0.y; oA.z = p1.x; oA.w = p1.y;
            oB.x = p2.x; oB.y = p2.y; oB.z = p3.x; oB.w = p3.y;
            float* op = &g_pO[ks * NQ * DIMC + (bq + q) * DIMC + h * HD + d0];
            *(float4*)op = oA; *(float4*)(op + 4) = oB;
        }
    }
}

// =============================================================================
// Kernel 5: output projection with split-combine folded into A-load.
// =============================================================================
__global__ void __launch_bounds__(128) gemm_final(
        const float* __restrict__ Wp, const float* __restrict__ bp_,
        float* __restrict__ out) {
    __shared__ float As[16][20];
    __shared__ float Ws[16][68];
    __shared__ float cw[16 * NH * 2];
    const int bm = blockIdx.y * 16;
    const int bn = blockIdx.x * 64;
    const int t  = threadIdx.x;

    {
        int q = t >> 3, hh = t & 7;
        int i1 = hh * NQ + bm + q;
        float m1 = g_pm[i1], m2 = g_pm[NH * NQ + i1];
        float s1 = g_ps[i1], s2 = g_ps[NH * NQ + i1];
        float M = fmaxf(m1, m2);
        float w1 = __expf(m1 - M), w2 = __expf(m2 - M);
        float inv = 1.0f / (w1 * s1 + w2 * s2);
        cw[(q * NH + hh) * 2]     = w1 * inv;
        cw[(q * NH + hh) * 2 + 1] = w2 * inv;
    }
    __syncthreads();

    const int ra = t >> 2, ka = (t & 3) * 4;
    const int kw = t >> 3, nw = (t & 7) * 8;
    const int ty = t >> 4, tx = t & 15;
    u64 acc2[2][2] = {{0ull, 0ull}, {0ull, 0ull}};
    for (int k0 = 0; k0 < DIMC; k0 += 16) {
        if (t < 64) {
            int c = k0 + ka;
            int hh = c >> 5;
            float4 o1 = *(const float4*)&g_pO[(bm + ra) * DIMC + c];
            float4 o2 = *(const float4*)&g_pO[NQ * DIMC + (bm + ra) * DIMC + c];
            float w1 = cw[(ra * NH + hh) * 2], w2 = cw[(ra * NH + hh) * 2 + 1];
            As[ka + 0][ra] = w1 * o1.x + w2 * o2.x;
            As[ka + 1][ra] = w1 * o1.y + w2 * o2.y;
            As[ka + 2][ra] = w1 * o1.z + w2 * o2.z;
            As[ka + 3][ra] = w1 * o1.w + w2 * o2.w;
        }
        *(float4*)&Ws[kw][nw]     = *(const float4*)&Wp[(k0 + kw) * DIMC + bn + nw];
        *(float4*)&Ws[kw][nw + 4] = *(const float4*)&Wp[(k0 + kw) * DIMC + bn + nw + 4];
        __syncthreads();
#pragma unroll
        for (int kk = 0; kk < 16; kk++) {
            float2 a2 = *(const float2*)&As[kk][ty * 2];
            ulonglong2 wp = *(const ulonglong2*)&Ws[kk][tx * 4];
            u64 ax = pk2(a2.x, a2.x), ay = pk2(a2.y, a2.y);
            fma2(acc2[0][0], ax, wp.x); fma2(acc2[0][1], ax, wp.y);
            fma2(acc2[1][0], ay, wp.x); fma2(acc2[1][1], ay, wp.y);
        }
        __syncthreads();
    }
    float4 bb = *(const float4*)&bp_[bn + tx * 4];
#pragma unroll
    for (int i = 0; i < 2; i++) {
        float2 p0 = up2(acc2[i][0]), p1 = up2(acc2[i][1]);
        float4 o;
        o.x = p0.x + bb.x; o.y = p0.y + bb.y;
        o.z = p1.x + bb.z; o.w = p1.y + bb.w;
        *(float4*)&out[(bm + ty * 2 + i) * DIMC + bn + tx * 4] = o;
    }
}

// =============================================================================
// Host side: fork gemm_qkv onto an aux stream, overlap with pwl_build+seg.
// Streams/events created once at load time (no device memory involved).
// =============================================================================
static cudaStream_t g_aux = nullptr;
static cudaEvent_t  g_efork = nullptr, g_ejoin = nullptr;
namespace {
struct StreamInit {
    StreamInit() {
        cudaStreamCreateWithFlags(&g_aux, cudaStreamNonBlocking);
        cudaEventCreateWithFlags(&g_efork, cudaEventDisableTiming);
        cudaEventCreateWithFlags(&g_ejoin, cudaEventDisableTiming);
    }
};
static StreamInit g_stream_init;
}

extern "C" void kernel_launch(void* const* d_in, const int* in_sizes, int n_in,
                              void* d_out, int out_size) {
    const float* query = (const float*)d_in[0];
    const float* kin   = (const float*)d_in[1];
    const float* vin   = (const float*)d_in[2];
    const float* pad   = (const float*)d_in[3];
    const float* am    = (const float*)d_in[4];
    const float* Wq    = (const float*)d_in[5];
    const float* bq    = (const float*)d_in[6];
    const float* Wk    = (const float*)d_in[7];
    const float* bk    = (const float*)d_in[8];
    const float* Wv    = (const float*)d_in[9];
    const float* bv    = (const float*)d_in[10];
    const float* Wp    = (const float*)d_in[11];
    const float* bp    = (const float*)d_in[12];
    const float* W1    = (const float*)d_in[13];
    const float* b1    = (const float*)d_in[14];
    const float* W2    = (const float*)d_in[15];
    float* out = (float*)d_out;

    cudaFuncSetAttribute(fused_attn, cudaFuncAttributeMaxDynamicSharedMemorySize, SMEM_BYTES);

    const bool fork = (g_aux != nullptr) && (g_efork != nullptr) && (g_ejoin != nullptr);

    if (fork) {
        // fork: aux stream runs gemm_qkv concurrently with pwl_build + seg_kernel
        cudaEventRecord(g_efork, 0);
        cudaStreamWaitEvent(g_aux, g_efork, 0);
        gemm_qkv<<<dim3(4, 32, 3), 128, 0, g_aux>>>(query, kin, vin, Wq, bq, Wk, bk, Wv, bv);
        pwl_build<<<1, 512>>>(W1, b1, W2);
        seg_kernel<<<NQ * NK / 1024, 256>>>(am);
        cudaEventRecord(g_ejoin, g_aux);
        cudaStreamWaitEvent(0, g_ejoin, 0);
    } else {
        pwl_build<<<1, 512>>>(W1, b1, W2);
        seg_kernel<<<NQ * NK / 1024, 256>>>(am);
        gemm_qkv<<<dim3(4, 32, 3), 128>>>(query, kin, vin, Wq, bq, Wk, bk, Wv, bv);
    }

    fused_attn<<<dim3(16, 8, 2), 256, SMEM_BYTES>>>(am, pad);
    gemm_final<<<dim3(4, 32), 128>>>(Wp, bp, out);
}